// round 16
// baseline (speedup 1.0000x reference)
#include <cuda_runtime.h>
#include <math.h>

#define T_STEPS 1024
#define K_FEAT  512
#define BLOCK   64
#define PF      128  // ring depth; T-PF = 896 = 7*128 exactly (no modular epilogue)

// One thread owns one (batch, feature) pair; serial 2-state affine scan over
// T=1024. R14 base (best: 41.4us kernel, DRAM 66.1%; __stwt stores, default
// loads) with ONE change: PF 64 -> 128. Probes the endpoint of the ring-depth
// curve (48: 64.7% -> 52: 65.8% -> 64: 66.1%). regs ~232 expected — under
// the 255 cap; if ptxas spills instead, this round is a clean negative and
// PF64 stands as final.
__global__ void __launch_bounds__(BLOCK) alpha_filter_kernel(
    const float* __restrict__ in,     // [B, T, K]
    const float* __restrict__ init,   // [K]
    const float* __restrict__ tau,    // [K]
    float* __restrict__ out)          // [B, T, K]
{
    const int k = blockIdx.x * BLOCK + threadIdx.x;
    const int b = blockIdx.y;

    // Per-feature coefficients (matches reference fp32 math)
    const float tc      = fmaxf(tau[k], 1e-8f);
    const float dt_tau  = 0.001f / tc;
    const float dt_tau2 = dt_tau / tc;
    const float e       = expf(-dt_tau);

    const float a00 = e * (1.0f - dt_tau);
    const float a01 = -e * dt_tau2;
    const float a10 = e * 0.001f;
    const float a11 = e * (1.0f + dt_tau);
    const float b0  = e * dt_tau2;
    const float b1  = 1.0f - a11;

    float x0 = 0.0f;
    float x1 = init[k];

    const size_t base = (size_t)b * T_STEPS * K_FEAT + (size_t)k;
    const float* ip = in  + base;
    float*       op = out + base;

    // Prologue: fill the prefetch ring with t = 0..PF-1
    float buf[PF];
#pragma unroll
    for (int i = 0; i < PF; ++i)
        buf[i] = ip[(size_t)i * K_FEAT];
    ip += (size_t)PF * K_FEAT;

    // Main loop: consume step t, ring-load step t+PF.
    // Steps that still load = T_STEPS - PF = 896 = 7 chunks of 128.
#pragma unroll 1
    for (int blk = 0; blk < (T_STEPS - PF) / PF; ++blk) {
#pragma unroll
        for (int i = 0; i < PF; ++i) {
            const float u = buf[i];
            buf[i] = ip[(size_t)i * K_FEAT];   // ring load: step t + PF
            const float nx0 = fmaf(a00, x0, fmaf(a01, x1, b0 * u));
            const float nx1 = fmaf(a10, x0, fmaf(a11, x1, b1 * u));
            x0 = nx0;
            x1 = nx1;
            __stwt(op + (size_t)i * K_FEAT, nx1);
        }
        ip += (size_t)PF * K_FEAT;
        op += (size_t)PF * K_FEAT;
    }

    // Epilogue: drain the last PF buffered inputs (no further loads;
    // ring index starts at 0 because PF divides T exactly).
#pragma unroll
    for (int i = 0; i < PF; ++i) {
        const float u = buf[i];
        const float nx0 = fmaf(a00, x0, fmaf(a01, x1, b0 * u));
        const float nx1 = fmaf(a10, x0, fmaf(a11, x1, b1 * u));
        x0 = nx0;
        x1 = nx1;
        __stwt(op + (size_t)i * K_FEAT, nx1);
    }
}

extern "C" void kernel_launch(void* const* d_in, const int* in_sizes, int n_in,
                              void* d_out, int out_size) {
    const float* inputs = (const float*)d_in[0];   // [B, T, K]
    const float* init   = (const float*)d_in[1];   // [K]
    const float* tau    = (const float*)d_in[2];   // [K]
    float*       out    = (float*)d_out;

    const int batch = in_sizes[0] / (T_STEPS * K_FEAT);   // 64
    dim3 grid(K_FEAT / BLOCK, batch);
    alpha_filter_kernel<<<grid, BLOCK>>>(inputs, init, tau, out);
}

// round 17
// speedup vs baseline: 1.0714x; 1.0714x over previous
#include <cuda_runtime.h>
#include <math.h>

#define T_STEPS 1024
#define K_FEAT  512
#define BLOCK   64
#define PF      96   // ring depth bisection: 64 (best, 168 regs) vs 128 (spill at 255)

// One thread owns one (batch, feature) pair; serial 2-state affine scan over
// T=1024. R14 base (best: 41.4us kernel, DRAM 66.1%; __stwt stores, default
// loads) with ONE change: PF 64 -> 96 (~200 regs expected — under the 255
// cap that killed PF128 via spill). Last open point on the ring-depth axis;
// if flat or worse, PF64 is final.
__global__ void __launch_bounds__(BLOCK) alpha_filter_kernel(
    const float* __restrict__ in,     // [B, T, K]
    const float* __restrict__ init,   // [K]
    const float* __restrict__ tau,    // [K]
    float* __restrict__ out)          // [B, T, K]
{
    const int k = blockIdx.x * BLOCK + threadIdx.x;
    const int b = blockIdx.y;

    // Per-feature coefficients (matches reference fp32 math)
    const float tc      = fmaxf(tau[k], 1e-8f);
    const float dt_tau  = 0.001f / tc;
    const float dt_tau2 = dt_tau / tc;
    const float e       = expf(-dt_tau);

    const float a00 = e * (1.0f - dt_tau);
    const float a01 = -e * dt_tau2;
    const float a10 = e * 0.001f;
    const float a11 = e * (1.0f + dt_tau);
    const float b0  = e * dt_tau2;
    const float b1  = 1.0f - a11;

    float x0 = 0.0f;
    float x1 = init[k];

    const size_t base = (size_t)b * T_STEPS * K_FEAT + (size_t)k;
    const float* ip = in  + base;
    float*       op = out + base;

    // Prologue: fill the prefetch ring with t = 0..PF-1
    float buf[PF];
#pragma unroll
    for (int i = 0; i < PF; ++i)
        buf[i] = ip[(size_t)i * K_FEAT];
    ip += (size_t)PF * K_FEAT;

    // Main loop: consume step t, ring-load step t+PF.
    // Steps that still load = T_STEPS - PF = 928 = 9 chunks of 96 + 64.
#pragma unroll 1
    for (int done = 0; done + PF <= T_STEPS - PF; done += PF) {
#pragma unroll
        for (int i = 0; i < PF; ++i) {
            const float u = buf[i];
            buf[i] = ip[(size_t)i * K_FEAT];   // ring load: step t + PF
            const float nx0 = fmaf(a00, x0, fmaf(a01, x1, b0 * u));
            const float nx1 = fmaf(a10, x0, fmaf(a11, x1, b1 * u));
            x0 = nx0;
            x1 = nx1;
            __stwt(op + (size_t)i * K_FEAT, nx1);
        }
        ip += (size_t)PF * K_FEAT;
        op += (size_t)PF * K_FEAT;
    }

    // Partial chunk: remaining steps that still ring-load.
    // (T_STEPS - PF) % PF = 928 % 96 = 64 steps.
#define REM ((T_STEPS - PF) % PF)
#if REM
#pragma unroll
    for (int i = 0; i < REM; ++i) {
        const float u = buf[i];
        buf[i] = ip[(size_t)i * K_FEAT];
        const float nx0 = fmaf(a00, x0, fmaf(a01, x1, b0 * u));
        const float nx1 = fmaf(a10, x0, fmaf(a11, x1, b1 * u));
        x0 = nx0;
        x1 = nx1;
        __stwt(op + (size_t)i * K_FEAT, nx1);
    }
    ip += (size_t)REM * K_FEAT;
    op += (size_t)REM * K_FEAT;
#endif

    // Epilogue: drain the last PF buffered inputs (no further loads).
    // Ring read order continues from index REM (mod PF).
#pragma unroll
    for (int i = 0; i < PF; ++i) {
        const int idx = (REM + i) % PF;
        const float u = buf[idx];
        const float nx0 = fmaf(a00, x0, fmaf(a01, x1, b0 * u));
        const float nx1 = fmaf(a10, x0, fmaf(a11, x1, b1 * u));
        x0 = nx0;
        x1 = nx1;
        __stwt(op + (size_t)i * K_FEAT, nx1);
    }
}

extern "C" void kernel_launch(void* const* d_in, const int* in_sizes, int n_in,
                              void* d_out, int out_size) {
    const float* inputs = (const float*)d_in[0];   // [B, T, K]
    const float* init   = (const float*)d_in[1];   // [K]
    const float* tau    = (const float*)d_in[2];   // [K]
    float*       out    = (float*)d_out;

    const int batch = in_sizes[0] / (T_STEPS * K_FEAT);   // 64
    dim3 grid(K_FEAT / BLOCK, batch);
    alpha_filter_kernel<<<grid, BLOCK>>>(inputs, init, tau, out);
}